// round 1
// baseline (speedup 1.0000x reference)
#include <cuda_runtime.h>
#include <math.h>

#define BSZ 8
#define SEQ 1024
#define DIM 1024
#define NH 16
#define HD 64
#define MTOT (BSZ*SEQ)      // 8192
#define DCAT (DIM+HD)       // 1088
#define DFF (2*DIM)         // 2048

// Scratch (allocation-free rule: __device__ globals)
__device__ float g_q[(size_t)BSZ*NH*SEQ*HD];
__device__ float g_k[(size_t)BSZ*NH*SEQ*HD];
__device__ float g_v[(size_t)BSZ*NH*SEQ*HD];
__device__ float g_cat[(size_t)MTOT*DCAT];
__device__ float g_h[(size_t)MTOT*DFF];

// ---------------------------------------------------------------------------
// Generic SGEMM: C[M,N] = A[M,K] @ B[K,N] + bias, optional relu.
// CTA tile 128x64, BK=16, 256 threads, 8x4 per thread. M%128==0, N%64==0, K%16==0.
// ---------------------------------------------------------------------------
template<bool RELU>
__global__ __launch_bounds__(256) void gemm_bias(
    const float* __restrict__ A, const float* __restrict__ B,
    const float* __restrict__ bias, float* __restrict__ C,
    int K, int N)
{
    __shared__ float As[16][128];
    __shared__ float Bs[16][64];
    const int tid = threadIdx.x;
    const int m0 = blockIdx.y * 128;
    const int n0 = blockIdx.x * 64;
    const int ty = tid >> 4, tx = tid & 15;
    const int bk_ = tid >> 4, bc = (tid & 15) * 4;

    float acc[8][4];
#pragma unroll
    for (int i = 0; i < 8; i++)
#pragma unroll
        for (int j = 0; j < 4; j++) acc[i][j] = 0.f;

    for (int k0 = 0; k0 < K; k0 += 16) {
#pragma unroll
        for (int j = 0; j < 2; j++) {
            int idx = tid * 2 + j;
            int r = idx >> 2, c4 = (idx & 3) << 2;
            const float4 va = *(const float4*)(A + (size_t)(m0 + r) * K + k0 + c4);
            As[c4 + 0][r] = va.x; As[c4 + 1][r] = va.y;
            As[c4 + 2][r] = va.z; As[c4 + 3][r] = va.w;
        }
        const float4 vb = *(const float4*)(B + (size_t)(k0 + bk_) * N + n0 + bc);
        *(float4*)(&Bs[bk_][bc]) = vb;
        __syncthreads();
#pragma unroll
        for (int kk = 0; kk < 16; kk++) {
            float a[8], b[4];
            *(float4*)(a)     = *(const float4*)(&As[kk][ty * 8]);
            *(float4*)(a + 4) = *(const float4*)(&As[kk][ty * 8 + 4]);
            *(float4*)(b)     = *(const float4*)(&Bs[kk][tx * 4]);
#pragma unroll
            for (int i = 0; i < 8; i++)
#pragma unroll
                for (int j = 0; j < 4; j++)
                    acc[i][j] = fmaf(a[i], b[j], acc[i][j]);
        }
        __syncthreads();
    }
#pragma unroll
    for (int i = 0; i < 8; i++) {
        int m = m0 + ty * 8 + i;
#pragma unroll
        for (int j = 0; j < 4; j++) {
            int c = n0 + tx * 4 + j;
            float v = acc[i][j] + bias[c];
            if (RELU) v = fmaxf(v, 0.f);
            C[(size_t)m * N + c] = v;
        }
    }
}

// ---------------------------------------------------------------------------
// Fused QKV + input projection GEMM. Logical N = 3136 = 16q|16k|16v|1in blocks
// of 64 columns. Each CTA column block lies entirely in one weight matrix.
// Scatters q (scaled), k, v into [b,h,n,d] and in_ into g_cat[:,1024:1088].
// ---------------------------------------------------------------------------
__global__ __launch_bounds__(256) void gemm_qkv(
    const float* __restrict__ x,
    const float* __restrict__ Wq, const float* __restrict__ bq,
    const float* __restrict__ Wk, const float* __restrict__ bk,
    const float* __restrict__ Wv, const float* __restrict__ bv,
    const float* __restrict__ Wi, const float* __restrict__ bi)
{
    __shared__ float As[16][128];
    __shared__ float Bs[16][64];
    const int tid = threadIdx.x;
    const int m0 = blockIdx.y * 128;
    const int n0 = blockIdx.x * 64;
    const int ty = tid >> 4, tx = tid & 15;
    const int bk_ = tid >> 4, bc = (tid & 15) * 4;

    const int seg = n0 >> 10;   // 0=q, 1=k, 2=v, 3=in (n0 = 3072 -> 3)
    const float* B; const float* bias; int Nb, nl0;
    if (seg == 0)      { B = Wq; bias = bq; Nb = DIM; nl0 = n0; }
    else if (seg == 1) { B = Wk; bias = bk; Nb = DIM; nl0 = n0 - 1024; }
    else if (seg == 2) { B = Wv; bias = bv; Nb = DIM; nl0 = n0 - 2048; }
    else               { B = Wi; bias = bi; Nb = HD;  nl0 = 0; }

    float acc[8][4];
#pragma unroll
    for (int i = 0; i < 8; i++)
#pragma unroll
        for (int j = 0; j < 4; j++) acc[i][j] = 0.f;

    for (int k0 = 0; k0 < DIM; k0 += 16) {
#pragma unroll
        for (int j = 0; j < 2; j++) {
            int idx = tid * 2 + j;
            int r = idx >> 2, c4 = (idx & 3) << 2;
            const float4 va = *(const float4*)(x + (size_t)(m0 + r) * DIM + k0 + c4);
            As[c4 + 0][r] = va.x; As[c4 + 1][r] = va.y;
            As[c4 + 2][r] = va.z; As[c4 + 3][r] = va.w;
        }
        const float4 vb = *(const float4*)(B + (size_t)(k0 + bk_) * Nb + nl0 + bc);
        *(float4*)(&Bs[bk_][bc]) = vb;
        __syncthreads();
#pragma unroll
        for (int kk = 0; kk < 16; kk++) {
            float a[8], b[4];
            *(float4*)(a)     = *(const float4*)(&As[kk][ty * 8]);
            *(float4*)(a + 4) = *(const float4*)(&As[kk][ty * 8 + 4]);
            *(float4*)(b)     = *(const float4*)(&Bs[kk][tx * 4]);
#pragma unroll
            for (int i = 0; i < 8; i++)
#pragma unroll
                for (int j = 0; j < 4; j++)
                    acc[i][j] = fmaf(a[i], b[j], acc[i][j]);
        }
        __syncthreads();
    }

#pragma unroll
    for (int i = 0; i < 8; i++) {
        int m = m0 + ty * 8 + i;
        int bidx = m >> 10, ni = m & 1023;
#pragma unroll
        for (int j = 0; j < 4; j++) {
            int cl = nl0 + tx * 4 + j;              // column within segment
            float v = acc[i][j] + bias[cl];
            if (seg == 3) {
                g_cat[(size_t)m * DCAT + DIM + cl] = v;
            } else {
                int h = cl >> 6, d = cl & 63;
                size_t idx = (((size_t)(bidx * NH + h)) * SEQ + ni) * HD + d;
                if (seg == 0)      g_q[idx] = v * 0.125f;   // HEAD_DIM^-0.5
                else if (seg == 1) g_k[idx] = v;
                else               g_v[idx] = v;
            }
        }
    }
}

// ---------------------------------------------------------------------------
// Attention: grid (16 q-tiles, 16 heads, 8 batch), 256 threads.
// 64 queries per CTA, quad of threads per query (d split 4x16),
// online softmax over 16-key chunks, diagonal masked.
// Writes to g_cat[:, h*64 : h*64+64].
// ---------------------------------------------------------------------------
__global__ __launch_bounds__(256) void attn_kernel()
{
    __shared__ float Ks[16][64];
    __shared__ float Vs[16][64];
    const int tid = threadIdx.x;
    const int b = blockIdx.z, h = blockIdx.y;
    const int qi = blockIdx.x * 64 + (tid >> 2);
    const int dsl = (tid & 3) * 16;
    const size_t head_off = ((size_t)(b * NH + h)) * SEQ * HD;

    float qf[16];
    {
        const float* qr = g_q + head_off + (size_t)qi * HD + dsl;
#pragma unroll
        for (int i = 0; i < 16; i += 4) *(float4*)(qf + i) = *(const float4*)(qr + i);
    }
    float acc[16];
#pragma unroll
    for (int i = 0; i < 16; i++) acc[i] = 0.f;
    float mx = -1e30f, l = 0.f;

    const float* kb = g_k + head_off;
    const float* vb = g_v + head_off;
    const int lr = tid >> 4, lc = (tid & 15) * 4;

    for (int c0 = 0; c0 < SEQ; c0 += 16) {
        __syncthreads();
        *(float4*)(&Ks[lr][lc]) = *(const float4*)(kb + (size_t)(c0 + lr) * HD + lc);
        *(float4*)(&Vs[lr][lc]) = *(const float4*)(vb + (size_t)(c0 + lr) * HD + lc);
        __syncthreads();

        float s[16];
#pragma unroll
        for (int j = 0; j < 16; j++) {
            const float4* kr = (const float4*)(&Ks[j][dsl]);
            float4 k0 = kr[0], k1 = kr[1], k2 = kr[2], k3 = kr[3];
            float p;
            p  = qf[0]  * k0.x + qf[1]  * k0.y + qf[2]  * k0.z + qf[3]  * k0.w;
            p += qf[4]  * k1.x + qf[5]  * k1.y + qf[6]  * k1.z + qf[7]  * k1.w;
            p += qf[8]  * k2.x + qf[9]  * k2.y + qf[10] * k2.z + qf[11] * k2.w;
            p += qf[12] * k3.x + qf[13] * k3.y + qf[14] * k3.z + qf[15] * k3.w;
            s[j] = p;
        }
        // reduce partial dots across the quad (lanes differ only in d-slice)
#pragma unroll
        for (int j = 0; j < 16; j++) {
            s[j] += __shfl_xor_sync(0xffffffffu, s[j], 1);
            s[j] += __shfl_xor_sync(0xffffffffu, s[j], 2);
        }
        float cm = -1e30f;
#pragma unroll
        for (int j = 0; j < 16; j++) {
            if (c0 + j == qi) s[j] = -1e30f;   // self position masked
            cm = fmaxf(cm, s[j]);
        }
        float mn = fmaxf(mx, cm);
        float sc = __expf(mx - mn);
        l *= sc;
#pragma unroll
        for (int i = 0; i < 16; i++) acc[i] *= sc;
        float p[16];
#pragma unroll
        for (int j = 0; j < 16; j++) { p[j] = __expf(s[j] - mn); l += p[j]; }
        mx = mn;
#pragma unroll
        for (int j = 0; j < 16; j++) {
            const float4* vr = (const float4*)(&Vs[j][dsl]);
            float4 v0 = vr[0], v1 = vr[1], v2 = vr[2], v3 = vr[3];
            acc[0]  += p[j] * v0.x; acc[1]  += p[j] * v0.y;
            acc[2]  += p[j] * v0.z; acc[3]  += p[j] * v0.w;
            acc[4]  += p[j] * v1.x; acc[5]  += p[j] * v1.y;
            acc[6]  += p[j] * v1.z; acc[7]  += p[j] * v1.w;
            acc[8]  += p[j] * v2.x; acc[9]  += p[j] * v2.y;
            acc[10] += p[j] * v2.z; acc[11] += p[j] * v2.w;
            acc[12] += p[j] * v3.x; acc[13] += p[j] * v3.y;
            acc[14] += p[j] * v3.z; acc[15] += p[j] * v3.w;
        }
    }
    float inv = 1.0f / l;
    float* orow = g_cat + (size_t)(b * SEQ + qi) * DCAT + h * HD + dsl;
#pragma unroll
    for (int i = 0; i < 16; i += 4) {
        float4 o;
        o.x = acc[i] * inv; o.y = acc[i + 1] * inv;
        o.z = acc[i + 2] * inv; o.w = acc[i + 3] * inv;
        *(float4*)(orow + i) = o;
    }
}

// ---------------------------------------------------------------------------
extern "C" void kernel_launch(void* const* d_in, const int* in_sizes, int n_in,
                              void* d_out, int out_size)
{
    const float* x   = (const float*)d_in[0];
    const float* Wq  = (const float*)d_in[1];
    const float* bq  = (const float*)d_in[2];
    const float* Wk  = (const float*)d_in[3];
    const float* bk  = (const float*)d_in[4];
    const float* Wv  = (const float*)d_in[5];
    const float* bv  = (const float*)d_in[6];
    const float* Wi  = (const float*)d_in[7];
    const float* bi  = (const float*)d_in[8];
    const float* W1  = (const float*)d_in[9];
    const float* b1  = (const float*)d_in[10];
    const float* W2  = (const float*)d_in[11];
    const float* b2  = (const float*)d_in[12];
    float* out = (float*)d_out;

    float *catp = nullptr, *hp = nullptr;
    cudaGetSymbolAddress((void**)&catp, g_cat);
    cudaGetSymbolAddress((void**)&hp, g_h);

    dim3 blk(256);
    // QKV + input projection: N = 3136 -> 49 column blocks, M = 8192 -> 64 row blocks
    gemm_qkv<<<dim3(49, MTOT / 128), blk>>>(x, Wq, bq, Wk, bk, Wv, bv, Wi, bi);
    // Attention
    attn_kernel<<<dim3(SEQ / 64, NH, BSZ), blk>>>();
    // FFN1: [8192,1088] @ [1088,2048] + b1, relu
    gemm_bias<true><<<dim3(DFF / 64, MTOT / 128), blk>>>(catp, W1, b1, hp, DCAT, DFF);
    // FFN2: [8192,2048] @ [2048,1024] + b2 -> out
    gemm_bias<false><<<dim3(DIM / 64, MTOT / 128), blk>>>(hp, W2, b2, out, DFF, DIM);
}

// round 2
// speedup vs baseline: 4.5494x; 4.5494x over previous
#include <cuda_runtime.h>
#include <math.h>

#define BSZ 8
#define SEQ 1024
#define DIM 1024
#define NH 16
#define HD 64
#define MTOT (BSZ*SEQ)      // 8192
#define DCAT (DIM+HD)       // 1088
#define DFF (2*DIM)         // 2048

// Scratch (allocation-free rule: __device__ globals)
__device__ float g_q[(size_t)BSZ*NH*SEQ*HD];
__device__ float g_k[(size_t)BSZ*NH*SEQ*HD];
__device__ float g_v[(size_t)BSZ*NH*SEQ*HD];
__device__ float g_cat[(size_t)MTOT*DCAT];
__device__ float g_h[(size_t)MTOT*DFF];

// ---------------------------------------------------------------------------
// tf32 mma helpers
// ---------------------------------------------------------------------------
__device__ __forceinline__ void mma_tf32(float c[4], const unsigned a[4], const unsigned b[2]) {
    asm volatile(
        "mma.sync.aligned.m16n8k8.row.col.f32.tf32.tf32.f32 "
        "{%0,%1,%2,%3}, {%4,%5,%6,%7}, {%8,%9}, {%0,%1,%2,%3};"
        : "+f"(c[0]), "+f"(c[1]), "+f"(c[2]), "+f"(c[3])
        : "r"(a[0]), "r"(a[1]), "r"(a[2]), "r"(a[3]), "r"(b[0]), "r"(b[1]));
}
__device__ __forceinline__ float to_tf32(float x) {
    unsigned u;
    asm("cvt.rna.tf32.f32 %0, %1;" : "=r"(u) : "f"(x));
    return __uint_as_float(u);
}
__device__ __forceinline__ float4 to_tf32_4(float4 v) {
    v.x = to_tf32(v.x); v.y = to_tf32(v.y); v.z = to_tf32(v.z); v.w = to_tf32(v.w);
    return v;
}
__device__ __forceinline__ unsigned fu(float x) { return __float_as_uint(x); }

// ---------------------------------------------------------------------------
// tf32 mma GEMM: C[M,N] = A[M,K] @ B[K,N] + bias (+relu).
// CTA 128x64, BK=32, 256 threads = 8 warps (4M x 2N), warp tile 32x32.
// Padded smem: As stride 36 (banks 4r+tg all distinct), Bs stride 72 (8tg+g).
// ---------------------------------------------------------------------------
#define ASTR 36
#define BSTR 72

template<bool RELU>
__global__ __launch_bounds__(256) void gemm_mma(
    const float* __restrict__ A, const float* __restrict__ B,
    const float* __restrict__ bias, float* __restrict__ C,
    int K, int N)
{
    __shared__ float As[128 * ASTR];
    __shared__ float Bs[32 * BSTR];
    const int tid = threadIdx.x;
    const int m0 = blockIdx.y * 128, n0 = blockIdx.x * 64;
    const int lane = tid & 31, warp = tid >> 5;
    const int wm = warp & 3, wn = warp >> 2;
    const int g = lane >> 2, tg = lane & 3;

    float acc[2][4][4];
#pragma unroll
    for (int mi = 0; mi < 2; mi++)
#pragma unroll
        for (int ni = 0; ni < 4; ni++)
#pragma unroll
            for (int r = 0; r < 4; r++) acc[mi][ni][r] = 0.f;

    for (int k0 = 0; k0 < K; k0 += 32) {
        // A tile: 128x32 = 1024 float4
#pragma unroll
        for (int i = 0; i < 4; i++) {
            int idx = i * 256 + tid;
            int r = idx >> 3, c4 = (idx & 7) * 4;
            float4 v = *(const float4*)(A + (size_t)(m0 + r) * K + k0 + c4);
            *(float4*)(As + r * ASTR + c4) = to_tf32_4(v);
        }
        // B tile: 32x64 = 512 float4
#pragma unroll
        for (int i = 0; i < 2; i++) {
            int idx = i * 256 + tid;
            int r = idx >> 4, c4 = (idx & 15) * 4;
            float4 v = *(const float4*)(B + (size_t)(k0 + r) * N + n0 + c4);
            *(float4*)(Bs + r * BSTR + c4) = to_tf32_4(v);
        }
        __syncthreads();
#pragma unroll
        for (int ks = 0; ks < 4; ks++) {
            const int kc = ks * 8;
            unsigned a[2][4], b[4][2];
#pragma unroll
            for (int mi = 0; mi < 2; mi++) {
                const float* p = As + (wm * 32 + mi * 16 + g) * ASTR + kc + tg;
                a[mi][0] = fu(p[0]);          a[mi][1] = fu(p[8 * ASTR]);
                a[mi][2] = fu(p[4]);          a[mi][3] = fu(p[8 * ASTR + 4]);
            }
#pragma unroll
            for (int ni = 0; ni < 4; ni++) {
                const float* p = Bs + (kc + tg) * BSTR + wn * 32 + ni * 8 + g;
                b[ni][0] = fu(p[0]);          b[ni][1] = fu(p[4 * BSTR]);
            }
#pragma unroll
            for (int mi = 0; mi < 2; mi++)
#pragma unroll
                for (int ni = 0; ni < 4; ni++)
                    mma_tf32(acc[mi][ni], a[mi], b[ni]);
        }
        __syncthreads();
    }

#pragma unroll
    for (int mi = 0; mi < 2; mi++) {
        int r = m0 + wm * 32 + mi * 16 + g;
#pragma unroll
        for (int ni = 0; ni < 4; ni++) {
            int c = n0 + wn * 32 + ni * 8 + 2 * tg;
            float b0 = bias[c], b1 = bias[c + 1];
            float v0 = acc[mi][ni][0] + b0, v1 = acc[mi][ni][1] + b1;
            float v2 = acc[mi][ni][2] + b0, v3 = acc[mi][ni][3] + b1;
            if (RELU) {
                v0 = fmaxf(v0, 0.f); v1 = fmaxf(v1, 0.f);
                v2 = fmaxf(v2, 0.f); v3 = fmaxf(v3, 0.f);
            }
            *(float2*)(C + (size_t)r * N + c)       = make_float2(v0, v1);
            *(float2*)(C + (size_t)(r + 8) * N + c) = make_float2(v2, v3);
        }
    }
}

// ---------------------------------------------------------------------------
// Fused QKV + input projection, tf32 mma. Logical N = 3136 = q|k|v (1024 each)
// then 64 for in_. Each 64-col block lies entirely in one weight. Scatters
// q (scaled), k, v into [b,h,n,d]; in_ into g_cat[:,1024:1088].
// ---------------------------------------------------------------------------
__global__ __launch_bounds__(256) void gemm_qkv_mma(
    const float* __restrict__ x,
    const float* __restrict__ Wq, const float* __restrict__ bq,
    const float* __restrict__ Wk, const float* __restrict__ bk,
    const float* __restrict__ Wv, const float* __restrict__ bv,
    const float* __restrict__ Wi, const float* __restrict__ bi)
{
    __shared__ float As[128 * ASTR];
    __shared__ float Bs[32 * BSTR];
    const int tid = threadIdx.x;
    const int m0 = blockIdx.y * 128, n0 = blockIdx.x * 64;
    const int lane = tid & 31, warp = tid >> 5;
    const int wm = warp & 3, wn = warp >> 2;
    const int g = lane >> 2, tg = lane & 3;

    const int seg = n0 >> 10;   // 0=q 1=k 2=v 3=in
    const float* B; const float* bias; int Nb, nl0;
    if (seg == 0)      { B = Wq; bias = bq; Nb = DIM; nl0 = n0; }
    else if (seg == 1) { B = Wk; bias = bk; Nb = DIM; nl0 = n0 - 1024; }
    else if (seg == 2) { B = Wv; bias = bv; Nb = DIM; nl0 = n0 - 2048; }
    else               { B = Wi; bias = bi; Nb = HD;  nl0 = 0; }

    float acc[2][4][4];
#pragma unroll
    for (int mi = 0; mi < 2; mi++)
#pragma unroll
        for (int ni = 0; ni < 4; ni++)
#pragma unroll
            for (int r = 0; r < 4; r++) acc[mi][ni][r] = 0.f;

    for (int k0 = 0; k0 < DIM; k0 += 32) {
#pragma unroll
        for (int i = 0; i < 4; i++) {
            int idx = i * 256 + tid;
            int r = idx >> 3, c4 = (idx & 7) * 4;
            float4 v = *(const float4*)(x + (size_t)(m0 + r) * DIM + k0 + c4);
            *(float4*)(As + r * ASTR + c4) = to_tf32_4(v);
        }
#pragma unroll
        for (int i = 0; i < 2; i++) {
            int idx = i * 256 + tid;
            int r = idx >> 4, c4 = (idx & 15) * 4;
            float4 v = *(const float4*)(B + (size_t)(k0 + r) * Nb + nl0 + c4);
            *(float4*)(Bs + r * BSTR + c4) = to_tf32_4(v);
        }
        __syncthreads();
#pragma unroll
        for (int ks = 0; ks < 4; ks++) {
            const int kc = ks * 8;
            unsigned a[2][4], b[4][2];
#pragma unroll
            for (int mi = 0; mi < 2; mi++) {
                const float* p = As + (wm * 32 + mi * 16 + g) * ASTR + kc + tg;
                a[mi][0] = fu(p[0]);          a[mi][1] = fu(p[8 * ASTR]);
                a[mi][2] = fu(p[4]);          a[mi][3] = fu(p[8 * ASTR + 4]);
            }
#pragma unroll
            for (int ni = 0; ni < 4; ni++) {
                const float* p = Bs + (kc + tg) * BSTR + wn * 32 + ni * 8 + g;
                b[ni][0] = fu(p[0]);          b[ni][1] = fu(p[4 * BSTR]);
            }
#pragma unroll
            for (int mi = 0; mi < 2; mi++)
#pragma unroll
                for (int ni = 0; ni < 4; ni++)
                    mma_tf32(acc[mi][ni], a[mi], b[ni]);
        }
        __syncthreads();
    }

#pragma unroll
    for (int mi = 0; mi < 2; mi++) {
#pragma unroll
        for (int rr = 0; rr < 2; rr++) {                 // rr=0: row g, rr=1: row g+8
            int m = m0 + wm * 32 + mi * 16 + g + rr * 8;
            int bidx = m >> 10, ni_seq = m & 1023;
#pragma unroll
            for (int ni = 0; ni < 4; ni++) {
                int cl = nl0 + wn * 32 + ni * 8 + 2 * tg;  // segment-local col
                float v0 = acc[mi][ni][rr * 2 + 0] + bias[cl];
                float v1 = acc[mi][ni][rr * 2 + 1] + bias[cl + 1];
                if (seg == 3) {
                    *(float2*)(g_cat + (size_t)m * DCAT + DIM + cl) = make_float2(v0, v1);
                } else {
                    int h = cl >> 6, d = cl & 63;          // cl,cl+1 same head
                    size_t idx = (((size_t)(bidx * NH + h)) * SEQ + ni_seq) * HD + d;
                    if (seg == 0) *(float2*)(g_q + idx) = make_float2(v0 * 0.125f, v1 * 0.125f);
                    else if (seg == 1) *(float2*)(g_k + idx) = make_float2(v0, v1);
                    else               *(float2*)(g_v + idx) = make_float2(v0, v1);
                }
            }
        }
    }
}

// ---------------------------------------------------------------------------
// Flash attention, tf32 mma. CTA = 128 threads (4 warps), 64 q-rows per CTA,
// one (b,h) per CTA, 32-key chunks. grid (16, 16, 8).
// S = Q·K^T via mma; online softmax in C-frag registers (quad shfl reduce);
// P re-laid out through per-warp padded smem; O += P·V via mma.
// ---------------------------------------------------------------------------
#define QSTR 68
#define KSTR 68
#define VSTR 72
#define PSTR 36

__global__ __launch_bounds__(128) void attn_mma()
{
    __shared__ float Qs[64 * QSTR];      // 17408 B
    __shared__ float Ks[32 * KSTR];      //  8704 B
    __shared__ float Vs[32 * VSTR];      //  9216 B
    __shared__ float Ps[4 * 16 * PSTR];  //  9216 B   (per-warp 16x32 P tile)

    const int tid = threadIdx.x, lane = tid & 31, warp = tid >> 5;
    const int g = lane >> 2, tg = lane & 3;
    const int b = blockIdx.z, h = blockIdx.y, q0 = blockIdx.x * 64;
    const size_t hoff = ((size_t)(b * NH + h)) * SEQ * HD;

    // Load Q tile 64x64 (already scaled by 0.125 at projection): 1024 float4
    {
        const float* qg = g_q + hoff + (size_t)q0 * HD;
#pragma unroll
        for (int i = 0; i < 8; i++) {
            int idx = i * 128 + tid;
            int r = idx >> 4, c4 = (idx & 15) * 4;
            float4 v = *(const float4*)(qg + r * HD + c4);
            *(float4*)(Qs + r * QSTR + c4) = to_tf32_4(v);
        }
    }

    float rowm[2] = {-1e30f, -1e30f};
    float rowl[2] = {0.f, 0.f};
    float o[8][4];
#pragma unroll
    for (int nf = 0; nf < 8; nf++)
#pragma unroll
        for (int r = 0; r < 4; r++) o[nf][r] = 0.f;

    const int qrow0 = q0 + warp * 16 + g;   // rows qrow0 and qrow0+8
    float* Pw = Ps + warp * 16 * PSTR;

    for (int c0 = 0; c0 < SEQ; c0 += 32) {
        __syncthreads();
        // Load K,V chunk 32x64 each: 512 float4 / 128 thr = 4 each
#pragma unroll
        for (int i = 0; i < 4; i++) {
            int idx = i * 128 + tid;
            int r = idx >> 4, c4 = (idx & 15) * 4;
            float4 kv = *(const float4*)(g_k + hoff + (size_t)(c0 + r) * HD + c4);
            *(float4*)(Ks + r * KSTR + c4) = to_tf32_4(kv);
            float4 vv = *(const float4*)(g_v + hoff + (size_t)(c0 + r) * HD + c4);
            *(float4*)(Vs + r * VSTR + c4) = to_tf32_4(vv);
        }
        __syncthreads();

        // S (16x32 per warp) = Q(16x64) · K^T
        float s[4][4];
#pragma unroll
        for (int ni = 0; ni < 4; ni++)
#pragma unroll
            for (int r = 0; r < 4; r++) s[ni][r] = 0.f;
#pragma unroll
        for (int ks = 0; ks < 8; ks++) {
            const int kc = ks * 8;
            unsigned a[4];
            const float* qp = Qs + (warp * 16 + g) * QSTR + kc + tg;
            a[0] = fu(qp[0]);       a[1] = fu(qp[8 * QSTR]);
            a[2] = fu(qp[4]);       a[3] = fu(qp[8 * QSTR + 4]);
#pragma unroll
            for (int ni = 0; ni < 4; ni++) {
                const float* kp = Ks + (ni * 8 + g) * KSTR + kc + tg;
                unsigned bb[2] = { fu(kp[0]), fu(kp[4]) };
                mma_tf32(s[ni], a, bb);
            }
        }

        // Diagonal mask + per-chunk row max
        float cm0 = -1e30f, cm1 = -1e30f;
#pragma unroll
        for (int ni = 0; ni < 4; ni++) {
            int col = c0 + ni * 8 + 2 * tg;
            if (col     == qrow0)     s[ni][0] = -1e30f;
            if (col + 1 == qrow0)     s[ni][1] = -1e30f;
            if (col     == qrow0 + 8) s[ni][2] = -1e30f;
            if (col + 1 == qrow0 + 8) s[ni][3] = -1e30f;
            cm0 = fmaxf(cm0, fmaxf(s[ni][0], s[ni][1]));
            cm1 = fmaxf(cm1, fmaxf(s[ni][2], s[ni][3]));
        }
        cm0 = fmaxf(cm0, __shfl_xor_sync(0xffffffffu, cm0, 1));
        cm0 = fmaxf(cm0, __shfl_xor_sync(0xffffffffu, cm0, 2));
        cm1 = fmaxf(cm1, __shfl_xor_sync(0xffffffffu, cm1, 1));
        cm1 = fmaxf(cm1, __shfl_xor_sync(0xffffffffu, cm1, 2));

        float mn0 = fmaxf(rowm[0], cm0), mn1 = fmaxf(rowm[1], cm1);
        float sc0 = __expf(rowm[0] - mn0), sc1 = __expf(rowm[1] - mn1);
        rowm[0] = mn0; rowm[1] = mn1;
        rowl[0] *= sc0; rowl[1] *= sc1;
#pragma unroll
        for (int nf = 0; nf < 8; nf++) {
            o[nf][0] *= sc0; o[nf][1] *= sc0;
            o[nf][2] *= sc1; o[nf][3] *= sc1;
        }

        float ls0 = 0.f, ls1 = 0.f;
#pragma unroll
        for (int ni = 0; ni < 4; ni++) {
            float p0 = __expf(s[ni][0] - mn0), p1 = __expf(s[ni][1] - mn0);
            float p2 = __expf(s[ni][2] - mn1), p3 = __expf(s[ni][3] - mn1);
            ls0 += p0 + p1; ls1 += p2 + p3;
            float* pp = Pw + g * PSTR + ni * 8 + 2 * tg;
            pp[0] = to_tf32(p0);            pp[1] = to_tf32(p1);
            pp[8 * PSTR] = to_tf32(p2);     pp[8 * PSTR + 1] = to_tf32(p3);
        }
        ls0 += __shfl_xor_sync(0xffffffffu, ls0, 1);
        ls0 += __shfl_xor_sync(0xffffffffu, ls0, 2);
        ls1 += __shfl_xor_sync(0xffffffffu, ls1, 1);
        ls1 += __shfl_xor_sync(0xffffffffu, ls1, 2);
        rowl[0] += ls0; rowl[1] += ls1;
        __syncwarp();

        // O += P(16x32) · V(32x64)
#pragma unroll
        for (int ks = 0; ks < 4; ks++) {
            const int kc = ks * 8;
            unsigned a[4];
            const float* pp = Pw + g * PSTR + kc + tg;
            a[0] = fu(pp[0]);       a[1] = fu(pp[8 * PSTR]);
            a[2] = fu(pp[4]);       a[3] = fu(pp[8 * PSTR + 4]);
#pragma unroll
            for (int nf = 0; nf < 8; nf++) {
                const float* vp = Vs + (kc + tg) * VSTR + nf * 8 + g;
                unsigned bb[2] = { fu(vp[0]), fu(vp[4 * VSTR]) };
                mma_tf32(o[nf], a, bb);
            }
        }
    }

    // Epilogue: normalize and store into g_cat[:, h*64 : h*64+64]
    float inv0 = 1.f / rowl[0], inv1 = 1.f / rowl[1];
    float* orow = g_cat + (size_t)(b * SEQ + qrow0) * DCAT + h * HD;
#pragma unroll
    for (int nf = 0; nf < 8; nf++) {
        int c = nf * 8 + 2 * tg;
        *(float2*)(orow + c)            = make_float2(o[nf][0] * inv0, o[nf][1] * inv0);
        *(float2*)(orow + 8 * DCAT + c) = make_float2(o[nf][2] * inv1, o[nf][3] * inv1);
    }
}

// ---------------------------------------------------------------------------
extern "C" void kernel_launch(void* const* d_in, const int* in_sizes, int n_in,
                              void* d_out, int out_size)
{
    const float* x   = (const float*)d_in[0];
    const float* Wq  = (const float*)d_in[1];
    const float* bq  = (const float*)d_in[2];
    const float* Wk  = (const float*)d_in[3];
    const float* bk  = (const float*)d_in[4];
    const float* Wv  = (const float*)d_in[5];
    const float* bv  = (const float*)d_in[6];
    const float* Wi  = (const float*)d_in[7];
    const float* bi  = (const float*)d_in[8];
    const float* W1  = (const float*)d_in[9];
    const float* b1  = (const float*)d_in[10];
    const float* W2  = (const float*)d_in[11];
    const float* b2  = (const float*)d_in[12];
    float* out = (float*)d_out;

    float *catp = nullptr, *hp = nullptr;
    cudaGetSymbolAddress((void**)&catp, g_cat);
    cudaGetSymbolAddress((void**)&hp, g_h);

    // QKV + input projection: N=3136 -> 49 col blocks, M=8192 -> 64 row blocks
    gemm_qkv_mma<<<dim3(49, 64), 256>>>(x, Wq, bq, Wk, bk, Wv, bv, Wi, bi);
    // Attention
    attn_mma<<<dim3(SEQ / 64, NH, BSZ), 128>>>();
    // FFN1: [8192,1088] @ [1088,2048] + b1, relu
    gemm_mma<true><<<dim3(DFF / 64, MTOT / 128), 256>>>(catp, W1, b1, hp, DCAT, DFF);
    // FFN2: [8192,2048] @ [2048,1024] + b2 -> out
    gemm_mma<false><<<dim3(DIM / 64, MTOT / 128), 256>>>(hp, W2, b2, out, DFF, DIM);
}